// round 16
// baseline (speedup 1.0000x reference)
#include <cuda_runtime.h>
#include <cuda_fp16.h>
#include <cstdint>
#include <math.h>

#define HH 56
#define WW 56
#define WS 7
#define SH 3
#define NHEAD 4
#define HD 32
#define CDIM 128
#define NTOK 49
#define NWIN 64
#define BIMG 64
#define MROWS (BIMG * NWIN * NTOK)   // 200704
#define LSEQ (HH * WW)
#define EPS 1e-5f

// ---------------- scratch ----------------
__device__ __half g_qkvh[(size_t)MROWS * 3 * CDIM];
__device__ __half g_atth[(size_t)MROWS * CDIM];
__device__ __half g_wqkv[384 * 128];
__device__ __half g_wproj[128 * 128];
__device__ __half g_wfc1[512 * 128];
__device__ __half g_wfc2[128 * 512];
__device__ __half g_biasMh[NHEAD * NTOK * NTOK];

// ---------------- ptx helpers ----------------
__device__ __forceinline__ unsigned smem_u32(const void* p) {
    return (unsigned)__cvta_generic_to_shared(p);
}
__device__ __forceinline__ unsigned h2_as_u32(__half2 h) {
    return *(unsigned*)&h;
}
__device__ __forceinline__ void cp16(unsigned dst, const void* src) {
    asm volatile("cp.async.cg.shared.global [%0], [%1], 16;" :: "r"(dst), "l"(src));
}
__device__ __forceinline__ void cp_commit() { asm volatile("cp.async.commit_group;"); }
__device__ __forceinline__ void cp_wait0() { asm volatile("cp.async.wait_group 0;"); }

__device__ __forceinline__ void ldsm4(unsigned* r, unsigned addr) {
    asm volatile("ldmatrix.sync.aligned.m8n8.x4.shared.b16 {%0,%1,%2,%3}, [%4];"
                 : "=r"(r[0]), "=r"(r[1]), "=r"(r[2]), "=r"(r[3]) : "r"(addr));
}
__device__ __forceinline__ void ldsm4t(unsigned* r, unsigned addr) {
    asm volatile("ldmatrix.sync.aligned.m8n8.x4.trans.shared.b16 {%0,%1,%2,%3}, [%4];"
                 : "=r"(r[0]), "=r"(r[1]), "=r"(r[2]), "=r"(r[3]) : "r"(addr));
}
__device__ __forceinline__ void mma_fp16(float* d, const unsigned* a, const unsigned* b) {
    asm volatile(
        "mma.sync.aligned.m16n8k16.row.col.f32.f16.f16.f32 "
        "{%0,%1,%2,%3}, {%4,%5,%6,%7}, {%8,%9}, {%0,%1,%2,%3};\n"
        : "+f"(d[0]), "+f"(d[1]), "+f"(d[2]), "+f"(d[3])
        : "r"(a[0]), "r"(a[1]), "r"(a[2]), "r"(a[3]), "r"(b[0]), "r"(b[1]));
}

// ---------------- fused weight convert + transpose ----------------
__global__ void convert_all(const float* __restrict__ qkv_w, const float* __restrict__ proj_w,
                            const float* __restrict__ fc1_w, const float* __restrict__ fc2_w,
                            __half* __restrict__ wqkv, __half* __restrict__ wproj,
                            __half* __restrict__ wfc1, __half* __restrict__ wfc2) {
    int i = blockIdx.x * 256 + threadIdx.x;
    if (i < 49152) {
        int k = i / 384, n = i % 384;
        wqkv[n * 128 + k] = __float2half(qkv_w[i]);
    } else if (i < 65536) {
        int j = i - 49152;
        int k = j / 128, n = j % 128;
        wproj[n * 128 + k] = __float2half(proj_w[j]);
    } else if (i < 131072) {
        int j = i - 65536;
        int k = j / 512, n = j % 512;
        wfc1[n * 128 + k] = __float2half(fc1_w[j]);
    } else if (i < 196608) {
        int j = i - 131072;
        int k = j / 128, n = j % 128;
        wfc2[n * 512 + k] = __float2half(fc2_w[j]);
    }
}

// ---------------- relative-position bias precompute (half) ----------------
__global__ void bias_pre(const float* __restrict__ rpb, __half* __restrict__ biasMh) {
    int i = blockIdx.x * 256 + threadIdx.x;
    if (i < NHEAD * NTOK * NTOK) {
        int h = i / (NTOK * NTOK);
        int r = i % (NTOK * NTOK);
        int n = r / NTOK, m = r % NTOK;
        int ridx = (n / WS - m / WS + WS - 1) * (2 * WS - 1) + (n % WS - m % WS + WS - 1);
        biasMh[i] = __float2half(rpb[ridx * NHEAD + h]);
    }
}

// ============ fused LN1 + roll/partition + QKV GEMM (v2: register LN + prefetch) ============
#define DSMEM_LNGEMM (34816 * 2)
__global__ void __launch_bounds__(256, 2)
ln_gemm(const float* __restrict__ X, const __half* __restrict__ Bt,
        const float* __restrict__ bias, const float* __restrict__ lng,
        const float* __restrict__ lnb, __half* __restrict__ C) {
    extern __shared__ char dyn[];
    __half (*As)[136] = (__half(*)[136])dyn;
    __half (*Bs)[136] = (__half(*)[136])(dyn + 34816);

    const int tid = threadIdx.x;
    const int lane = tid & 31, wid = tid >> 5;
    const int m0 = blockIdx.x * 128;

    // prefetch weight chunk 0 while LN runs
    #pragma unroll
    for (int t = 0; t < 8; t++) {
        int i = tid + t * 256;
        int row = i >> 4;
        int col = (i & 15) * 8;
        cp16(smem_u32(&Bs[row][col]), &Bt[(long)row * CDIM + col]);
    }
    cp_commit();

    // ---- register LN: warp owns 16 rows; lane owns cols lane*4..lane*4+3 ----
    const int c0 = lane * 4;
    const float4 g4 = *(const float4*)&lng[c0];
    const float4 b4 = *(const float4*)&lnb[c0];
    for (int rr = 0; rr < 16; rr++) {
        int row = wid * 16 + rr;
        int R = m0 + row;
        int bi = R / (NWIN * NTOK);
        int tt = R % (NWIN * NTOK);
        int win = tt / NTOK, n = tt % NTOK;
        int hh = (win / 8) * WS + n / WS;
        int ww = (win % 8) * WS + n % WS;
        long srow = (long)bi * LSEQ + ((hh + SH) % HH) * WW + (ww + SH) % WW;

        float4 v = *(const float4*)&X[srow * CDIM + c0];
        float s = v.x + v.y + v.z + v.w;
        float s2 = v.x * v.x + v.y * v.y + v.z * v.z + v.w * v.w;
        #pragma unroll
        for (int o = 16; o; o >>= 1) {
            s += __shfl_xor_sync(0xffffffffu, s, o);
            s2 += __shfl_xor_sync(0xffffffffu, s2, o);
        }
        float mu = s * (1.f / 128.f);
        float inv = rsqrtf(s2 * (1.f / 128.f) - mu * mu + EPS);
        __half2 h0 = __floats2half2_rn((v.x - mu) * inv * g4.x + b4.x,
                                       (v.y - mu) * inv * g4.y + b4.y);
        __half2 h1 = __floats2half2_rn((v.z - mu) * inv * g4.z + b4.z,
                                       (v.w - mu) * inv * g4.w + b4.w);
        *(__half2*)&As[row][c0] = h0;
        *(__half2*)&As[row][c0 + 2] = h1;
    }
    cp_wait0();
    __syncthreads();   // As + Bs(chunk0) ready

    const int a_row = (lane & 7) + ((lane >> 3) & 1) * 8;
    const int a_kc  = ((lane >> 4) & 1) * 8;
    const int b_row = (lane & 7) + ((lane >> 4) & 1) * 8;
    const int b_kc  = ((lane >> 3) & 1) * 8;
    const int wm = (wid & 1) * 64;
    const int wn = (wid >> 1) * 32;
    const int g = lane >> 2, tg = lane & 3;

    for (int c = 0; c < 3; c++) {
        float acc[4][4][4];
        #pragma unroll
        for (int i = 0; i < 4; i++)
            #pragma unroll
            for (int j = 0; j < 4; j++)
                #pragma unroll
                for (int r = 0; r < 4; r++) acc[i][j][r] = 0.f;

        #pragma unroll
        for (int it = 0; it < 8; it++) {
            const int k0 = it * 16;
            unsigned a_frag[4][4], b_frag[4][2];
            #pragma unroll
            for (int mi = 0; mi < 4; mi++)
                ldsm4(a_frag[mi], smem_u32(&As[wm + mi * 16 + a_row][k0 + a_kc]));
            #pragma unroll
            for (int n2 = 0; n2 < 2; n2++) {
                unsigned r4[4];
                ldsm4(r4, smem_u32(&Bs[wn + n2 * 16 + b_row][k0 + b_kc]));
                b_frag[2 * n2][0] = r4[0]; b_frag[2 * n2][1] = r4[1];
                b_frag[2 * n2 + 1][0] = r4[2]; b_frag[2 * n2 + 1][1] = r4[3];
            }
            #pragma unroll
            for (int mi = 0; mi < 4; mi++)
                #pragma unroll
                for (int ni = 0; ni < 4; ni++)
                    mma_fp16(acc[mi][ni], a_frag[mi], b_frag[ni]);
        }
        __syncthreads();   // Bs reads for chunk c done

        // prefetch chunk c+1 under the epilogue stores
        if (c + 1 < 3) {
            #pragma unroll
            for (int t = 0; t < 8; t++) {
                int i = tid + t * 256;
                int row = i >> 4;
                int col = (i & 15) * 8;
                cp16(smem_u32(&Bs[row][col]), &Bt[(long)((c + 1) * 128 + row) * CDIM + col]);
            }
            cp_commit();
        }

        #pragma unroll
        for (int mi = 0; mi < 4; mi++) {
            #pragma unroll
            for (int hf = 0; hf < 2; hf++) {
                int row = m0 + wm + mi * 16 + g + hf * 8;
                #pragma unroll
                for (int ni = 0; ni < 4; ni++) {
                    int col = c * 128 + wn + ni * 8 + 2 * tg;
                    float v0 = acc[mi][ni][hf * 2 + 0] + bias[col];
                    float v1 = acc[mi][ni][hf * 2 + 1] + bias[col + 1];
                    *(__half2*)&C[(long)row * 384 + col] = __floats2half2_rn(v0, v1);
                }
            }
        }

        if (c + 1 < 3) {
            cp_wait0();
            __syncthreads();
        }
    }
}

// ============ MEGA: proj + residual + LN2 + fc1(GELU) + fc2 + residual + scatter ============
#define DSMEM_MEGA (34816 * 3 + 4096)
__global__ void __launch_bounds__(256)
mega_mlp(const __half* __restrict__ atth, const __half* __restrict__ wproj,
         const float* __restrict__ pbias, const float* __restrict__ x,
         const float* __restrict__ lng, const float* __restrict__ lnb,
         const __half* __restrict__ wfc1, const float* __restrict__ f1bias,
         const __half* __restrict__ wfc2, const float* __restrict__ f2bias,
         float* __restrict__ out) {
    extern __shared__ char dyn[];
    __half (*As)[136] = (__half(*)[136])dyn;
    __half (*Bs)[136] = (__half(*)[136])(dyn + 34816);
    __half (*Hs)[136] = (__half(*)[136])(dyn + 69632);
    float (*redS)[128] = (float(*)[128])(dyn + 104448);
    float (*redQ)[128] = (float(*)[128])(dyn + 104448 + 2048);

    const int tid = threadIdx.x;
    const int lane = tid & 31, wid = tid >> 5;
    const int m0 = blockIdx.x * 128;

    const int a_row = (lane & 7) + ((lane >> 3) & 1) * 8;
    const int a_kc  = ((lane >> 4) & 1) * 8;
    const int b_row = (lane & 7) + ((lane >> 4) & 1) * 8;
    const int b_kc  = ((lane >> 3) & 1) * 8;
    const int wm = (wid & 1) * 64;
    const int wn = (wid >> 1) * 32;
    const int g = lane >> 2, tg = lane & 3;

    // ---- stage 1: proj GEMM ----
    #pragma unroll
    for (int t = 0; t < 8; t++) {
        int i = tid + t * 256;
        int row = i >> 4;
        int col = (i & 15) * 8;
        cp16(smem_u32(&As[row][col]), &atth[(long)(m0 + row) * CDIM + col]);
        cp16(smem_u32(&Bs[row][col]), &wproj[row * CDIM + col]);
    }
    cp_commit();
    cp_wait0();
    __syncthreads();

    float acc[4][4][4];
    #pragma unroll
    for (int i = 0; i < 4; i++)
        #pragma unroll
        for (int j = 0; j < 4; j++)
            #pragma unroll
            for (int r = 0; r < 4; r++) acc[i][j][r] = 0.f;

    #pragma unroll
    for (int it = 0; it < 8; it++) {
        const int k0 = it * 16;
        unsigned a_frag[4][4], b_frag[4][2];
        #pragma unroll
        for (int mi = 0; mi < 4; mi++)
            ldsm4(a_frag[mi], smem_u32(&As[wm + mi * 16 + a_row][k0 + a_kc]));
        #pragma unroll
        for (int n2 = 0; n2 < 2; n2++) {
            unsigned r4[4];
            ldsm4(r4, smem_u32(&Bs[wn + n2 * 16 + b_row][k0 + b_kc]));
            b_frag[2 * n2][0] = r4[0]; b_frag[2 * n2][1] = r4[1];
            b_frag[2 * n2 + 1][0] = r4[2]; b_frag[2 * n2 + 1][1] = r4[3];
        }
        #pragma unroll
        for (int mi = 0; mi < 4; mi++)
            #pragma unroll
            for (int ni = 0; ni < 4; ni++)
                mma_fp16(acc[mi][ni], a_frag[mi], b_frag[ni]);
    }
    __syncthreads();

    // ---- stage 2: y = acc + pbias + x[gather]; LN partial sums ----
    #pragma unroll
    for (int mi = 0; mi < 4; mi++) {
        #pragma unroll
        for (int hf = 0; hf < 2; hf++) {
            int lrow = wm + mi * 16 + g + hf * 8;
            int R = m0 + lrow;
            int bi = R / (NWIN * NTOK);
            int tt = R % (NWIN * NTOK);
            int win = tt / NTOK, n = tt % NTOK;
            int hh = (win / 8) * WS + n / WS;
            int ww = (win % 8) * WS + n % WS;
            long srow = (long)bi * LSEQ + ((hh + SH) % HH) * WW + (ww + SH) % WW;

            float s = 0.f, s2 = 0.f;
            #pragma unroll
            for (int ni = 0; ni < 4; ni++) {
                int col = wn + ni * 8 + 2 * tg;
                float2 xr = *(const float2*)&x[srow * CDIM + col];
                float v0 = acc[mi][ni][hf * 2 + 0] + pbias[col] + xr.x;
                float v1 = acc[mi][ni][hf * 2 + 1] + pbias[col + 1] + xr.y;
                acc[mi][ni][hf * 2 + 0] = v0;
                acc[mi][ni][hf * 2 + 1] = v1;
                s += v0 + v1;
                s2 += v0 * v0 + v1 * v1;
            }
            s += __shfl_xor_sync(0xffffffffu, s, 1);
            s += __shfl_xor_sync(0xffffffffu, s, 2);
            s2 += __shfl_xor_sync(0xffffffffu, s2, 1);
            s2 += __shfl_xor_sync(0xffffffffu, s2, 2);
            if (tg == 0) {
                redS[wid >> 1][lrow] = s;
                redQ[wid >> 1][lrow] = s2;
            }
        }
    }
    __syncthreads();

    // ---- stage 3: LN'd -> As; acc becomes out accumulator (y + fc2 bias) ----
    #pragma unroll
    for (int mi = 0; mi < 4; mi++) {
        #pragma unroll
        for (int hf = 0; hf < 2; hf++) {
            int lrow = wm + mi * 16 + g + hf * 8;
            float s = redS[0][lrow] + redS[1][lrow] + redS[2][lrow] + redS[3][lrow];
            float s2 = redQ[0][lrow] + redQ[1][lrow] + redQ[2][lrow] + redQ[3][lrow];
            float mu = s * (1.f / 128.f);
            float inv = rsqrtf(s2 * (1.f / 128.f) - mu * mu + EPS);
            #pragma unroll
            for (int ni = 0; ni < 4; ni++) {
                int col = wn + ni * 8 + 2 * tg;
                float y0 = acc[mi][ni][hf * 2 + 0];
                float y1 = acc[mi][ni][hf * 2 + 1];
                float v0 = (y0 - mu) * inv * lng[col] + lnb[col];
                float v1 = (y1 - mu) * inv * lng[col + 1] + lnb[col + 1];
                *(__half2*)&As[lrow][col] = __floats2half2_rn(v0, v1);
                acc[mi][ni][hf * 2 + 0] = y0 + f2bias[col];
                acc[mi][ni][hf * 2 + 1] = y1 + f2bias[col + 1];
            }
        }
    }
    __syncthreads();

    // ---- stage 4: 4 chunks of fc1(GELU) -> Hs -> fc2 accumulate into acc ----
    for (int c = 0; c < 4; c++) {
        #pragma unroll
        for (int t = 0; t < 8; t++) {
            int i = tid + t * 256;
            int row = i >> 4;
            int col = (i & 15) * 8;
            cp16(smem_u32(&Bs[row][col]), &wfc1[(long)(c * 128 + row) * CDIM + col]);
        }
        cp_commit();
        cp_wait0();
        __syncthreads();

        float fa[4][4][4];
        #pragma unroll
        for (int i = 0; i < 4; i++)
            #pragma unroll
            for (int j = 0; j < 4; j++)
                #pragma unroll
                for (int r = 0; r < 4; r++) fa[i][j][r] = 0.f;

        #pragma unroll
        for (int it = 0; it < 8; it++) {
            const int k0 = it * 16;
            unsigned a_frag[4][4], b_frag[4][2];
            #pragma unroll
            for (int mi = 0; mi < 4; mi++)
                ldsm4(a_frag[mi], smem_u32(&As[wm + mi * 16 + a_row][k0 + a_kc]));
            #pragma unroll
            for (int n2 = 0; n2 < 2; n2++) {
                unsigned r4[4];
                ldsm4(r4, smem_u32(&Bs[wn + n2 * 16 + b_row][k0 + b_kc]));
                b_frag[2 * n2][0] = r4[0]; b_frag[2 * n2][1] = r4[1];
                b_frag[2 * n2 + 1][0] = r4[2]; b_frag[2 * n2 + 1][1] = r4[3];
            }
            #pragma unroll
            for (int mi = 0; mi < 4; mi++)
                #pragma unroll
                for (int ni = 0; ni < 4; ni++)
                    mma_fp16(fa[mi][ni], a_frag[mi], b_frag[ni]);
        }
        __syncthreads();

        #pragma unroll
        for (int t = 0; t < 8; t++) {
            int i = tid + t * 256;
            int row = i >> 4;
            int col = (i & 15) * 8;
            cp16(smem_u32(&Bs[row][col]), &wfc2[(long)row * 512 + c * 128 + col]);
        }
        cp_commit();

        #pragma unroll
        for (int mi = 0; mi < 4; mi++) {
            #pragma unroll
            for (int hf = 0; hf < 2; hf++) {
                int lrow = wm + mi * 16 + g + hf * 8;
                #pragma unroll
                for (int ni = 0; ni < 4; ni++) {
                    int col = c * 128 + wn + ni * 8 + 2 * tg;
                    float v0 = fa[mi][ni][hf * 2 + 0] + f1bias[col];
                    float v1 = fa[mi][ni][hf * 2 + 1] + f1bias[col + 1];
                    v0 = 0.5f * v0 * (1.0f + erff(v0 * 0.70710678118654752f));
                    v1 = 0.5f * v1 * (1.0f + erff(v1 * 0.70710678118654752f));
                    *(__half2*)&Hs[lrow][(col & 127)] = __floats2half2_rn(v0, v1);
                }
            }
        }
        cp_wait0();
        __syncthreads();

        #pragma unroll
        for (int it = 0; it < 8; it++) {
            const int k0 = it * 16;
            unsigned a_frag[4][4], b_frag[4][2];
            #pragma unroll
            for (int mi = 0; mi < 4; mi++)
                ldsm4(a_frag[mi], smem_u32(&Hs[wm + mi * 16 + a_row][k0 + a_kc]));
            #pragma unroll
            for (int n2 = 0; n2 < 2; n2++) {
                unsigned r4[4];
                ldsm4(r4, smem_u32(&Bs[wn + n2 * 16 + b_row][k0 + b_kc]));
                b_frag[2 * n2][0] = r4[0]; b_frag[2 * n2][1] = r4[1];
                b_frag[2 * n2 + 1][0] = r4[2]; b_frag[2 * n2 + 1][1] = r4[3];
            }
            #pragma unroll
            for (int mi = 0; mi < 4; mi++)
                #pragma unroll
                for (int ni = 0; ni < 4; ni++)
                    mma_fp16(acc[mi][ni], a_frag[mi], b_frag[ni]);
        }
        __syncthreads();
    }

    // ---- stage 5: scatter out ----
    #pragma unroll
    for (int mi = 0; mi < 4; mi++) {
        #pragma unroll
        for (int hf = 0; hf < 2; hf++) {
            int R = m0 + wm + mi * 16 + g + hf * 8;
            int bi = R / (NWIN * NTOK);
            int tt = R % (NWIN * NTOK);
            int win = tt / NTOK, n = tt % NTOK;
            int hh = (win / 8) * WS + n / WS;
            int ww = (win % 8) * WS + n % WS;
            long drow = (long)bi * LSEQ + ((hh + SH) % HH) * WW + (ww + SH) % WW;
            #pragma unroll
            for (int ni = 0; ni < 4; ni++) {
                int col = wn + ni * 8 + 2 * tg;
                *(float2*)&out[drow * CDIM + col] =
                    make_float2(acc[mi][ni][hf * 2 + 0], acc[mi][ni][hf * 2 + 1]);
            }
        }
    }
}

// ============ tensor-core window attention ============
#define ATT_TILE (64 * 40)
#define ATT_SM_Q 0
#define ATT_SM_K (4 * ATT_TILE * 2)
#define ATT_SM_V (8 * ATT_TILE * 2)
#define ATT_SM_B (12 * ATT_TILE * 2)
#define ATT_SM_L (ATT_SM_B + 49 * 50 * 2 + 28)
#define DSMEM_ATT (ATT_SM_L + 4 * 64 * 4)
__global__ void __launch_bounds__(512)
attn_mma(const __half* __restrict__ qkv,
         const __half* __restrict__ biasMh,
         __half* __restrict__ out) {
    extern __shared__ char dynA[];
    __half (*Qs)[64][40] = (__half(*)[64][40])(dynA + ATT_SM_Q);
    __half (*Ks)[64][40] = (__half(*)[64][40])(dynA + ATT_SM_K);
    __half (*Vs)[64][40] = (__half(*)[64][40])(dynA + ATT_SM_V);
    __half (*bias_s)[50] = (__half(*)[50])(dynA + ATT_SM_B);
    int (*lab)[64] = (int(*)[64])(dynA + ATT_SM_L);

    const int head = blockIdx.y;
    const int tid = threadIdx.x;
    const int gtid = tid & 127;
    const int grp = tid >> 7;
    const int wg = blockIdx.x * 4 + grp;
    const int lane = tid & 31;
    const int lwid = (tid >> 5) & 3;
    const int g = lane >> 2, tg = lane & 3;

    const int wi = wg & (NWIN - 1);
    const bool need_mask = ((wi >> 3) == 7) || ((wi & 7) == 7);

    for (int i = gtid; i < 15 * 40; i += 128)
        Vs[grp][49 + i / 40][i % 40] = __float2half(0.f);

    if (need_mask && gtid < 64) {
        int t = gtid < NTOK ? gtid : 0;
        int h = (wi / 8) * WS + t / WS;
        int w = (wi % 8) * WS + t % WS;
        int rh = (h < HH - WS) ? 0 : ((h < HH - SH) ? 1 : 2);
        int rw = (w < WW - WS) ? 0 : ((w < WW - SH) ? 1 : 2);
        lab[grp][gtid] = rh * 3 + rw;
    }

    for (int i = tid; i < NTOK * NTOK; i += 512) {
        int n = i / NTOK, m = i % NTOK;
        bias_s[n][m] = biasMh[head * NTOK * NTOK + i];
    }

    const __half2 scale2 = __float2half2_rn(0.1767766952966369f);
    for (int i = gtid; i < NTOK * 4; i += 128) {
        int r = i >> 2, c8 = (i & 3) * 8;
        long base = ((long)wg * NTOK + r) * 384 + c8 + head * 32;
        uint4 qv = *(const uint4*)&qkv[base];
        __half2* qh = (__half2*)&qv;
        #pragma unroll
        for (int j = 0; j < 4; j++) qh[j] = __hmul2(qh[j], scale2);
        *(uint4*)&Qs[grp][r][c8] = qv;
        *(uint4*)&Ks[grp][r][c8] = *(const uint4*)&qkv[base + 128];
        *(uint4*)&Vs[grp][r][c8] = *(const uint4*)&qkv[base + 256];
    }
    __syncthreads();

    const int a_row = (lane & 7) + ((lane >> 3) & 1) * 8;
    const int a_kc  = ((lane >> 4) & 1) * 8;
    const int b_row = (lane & 7) + ((lane >> 4) & 1) * 8;
    const int b_kc  = ((lane >> 3) & 1) * 8;
    const int t_row = (lane & 7) + ((lane >> 3) & 1) * 8;
    const int t_col = (lane >> 4) * 8;
    const int w16 = lwid * 16;

    float sa[8][4];
    #pragma unroll
    for (int i = 0; i < 8; i++)
        #pragma unroll
        for (int r = 0; r < 4; r++) sa[i][r] = 0.f;

    #pragma unroll
    for (int kc = 0; kc < 2; kc++) {
        unsigned aq[4];
        ldsm4(aq, smem_u32(&Qs[grp][w16 + a_row][kc * 16 + a_kc]));
        #pragma unroll
        for (int nt = 0; nt < 4; nt++) {
            unsigned r4[4];
            ldsm4(r4, smem_u32(&Ks[grp][nt * 16 + b_row][kc * 16 + b_kc]));
            unsigned b0[2] = {r4[0], r4[1]};
            unsigned b1[2] = {r4[2], r4[3]};
            mma_fp16(sa[2 * nt], aq, b0);
            mma_fp16(sa[2 * nt + 1], aq, b1);
        }
    }

    const int rowA = w16 + g;
    const int rowB = w16 + g + 8;
    const int rA = rowA < NTOK ? rowA : 0;
    const int rB = rowB < NTOK ? rowB : 0;
    #pragma unroll
    for (int ni = 0; ni < 6; ni++) {
        float2 fA = __half22float2(*(__half2*)&bias_s[rA][8 * ni + 2 * tg]);
        float2 fB = __half22float2(*(__half2*)&bias_s[rB][8 * ni + 2 * tg]);
        sa[ni][0] += fA.x; sa[ni][1] += fA.y;
        sa[ni][2] += fB.x; sa[ni][3] += fB.y;
    }
    if (tg == 0) {
        sa[6][0] += __half2float(bias_s[rA][48]);
        sa[6][2] += __half2float(bias_s[rB][48]);
        sa[6][1] = -1e30f; sa[6][3] = -1e30f;
    } else {
        sa[6][0] = sa[6][1] = sa[6][2] = sa[6][3] = -1e30f;
    }
    sa[7][0] = sa[7][1] = sa[7][2] = sa[7][3] = -1e30f;

    if (need_mask) {
        const int labA = lab[grp][rA], labB = lab[grp][rB];
        #pragma unroll
        for (int ni = 0; ni < 7; ni++) {
            #pragma unroll
            for (int cc = 0; cc < 2; cc++) {
                int m = 8 * ni + 2 * tg + cc;
                if (m < NTOK) {
                    int lm = lab[grp][m];
                    if (lm != labA) sa[ni][cc] -= 100.f;
                    if (lm != labB) sa[ni][cc + 2] -= 100.f;
                }
            }
        }
    }

    float mxA = -1e30f, mxB = -1e30f;
    #pragma unroll
    for (int ni = 0; ni < 8; ni++) {
        mxA = fmaxf(mxA, fmaxf(sa[ni][0], sa[ni][1]));
        mxB = fmaxf(mxB, fmaxf(sa[ni][2], sa[ni][3]));
    }
    #pragma unroll
    for (int o = 1; o <= 2; o <<= 1) {
        mxA = fmaxf(mxA, __shfl_xor_sync(0xffffffffu, mxA, o));
        mxB = fmaxf(mxB, __shfl_xor_sync(0xffffffffu, mxB, o));
    }
    float smA = 0.f, smB = 0.f;
    #pragma unroll
    for (int ni = 0; ni < 8; ni++) {
        sa[ni][0] = __expf(sa[ni][0] - mxA); smA += sa[ni][0];
        sa[ni][1] = __expf(sa[ni][1] - mxA); smA += sa[ni][1];
        sa[ni][2] = __expf(sa[ni][2] - mxB); smB += sa[ni][2];
        sa[ni][3] = __expf(sa[ni][3] - mxB); smB += sa[ni][3];
    }
    #pragma unroll
    for (int o = 1; o <= 2; o <<= 1) {
        smA += __shfl_xor_sync(0xffffffffu, smA, o);
        smB += __shfl_xor_sync(0xffffffffu, smB, o);
    }
    const float ivA = 1.0f / smA, ivB = 1.0f / smB;

    unsigned ap[4][4];
    #pragma unroll
    for (int kc = 0; kc < 4; kc++) {
        ap[kc][0] = h2_as_u32(__floats2half2_rn(sa[2 * kc][0] * ivA, sa[2 * kc][1] * ivA));
        ap[kc][1] = h2_as_u32(__floats2half2_rn(sa[2 * kc][2] * ivB, sa[2 * kc][3] * ivB));
        ap[kc][2] = h2_as_u32(__floats2half2_rn(sa[2 * kc + 1][0] * ivA, sa[2 * kc + 1][1] * ivA));
        ap[kc][3] = h2_as_u32(__floats2half2_rn(sa[2 * kc + 1][2] * ivB, sa[2 * kc + 1][3] * ivB));
    }

    float oa[4][4];
    #pragma unroll
    for (int i = 0; i < 4; i++)
        #pragma unroll
        for (int r = 0; r < 4; r++) oa[i][r] = 0.f;

    #pragma unroll
    for (int kc = 0; kc < 4; kc++) {
        #pragma unroll
        for (int nt = 0; nt < 2; nt++) {
            unsigned r4[4];
            ldsm4t(r4, smem_u32(&Vs[grp][kc * 16 + t_row][nt * 16 + t_col]));
            unsigned b0[2] = {r4[0], r4[1]};
            unsigned b1[2] = {r4[2], r4[3]};
            mma_fp16(oa[2 * nt], ap[kc], b0);
            mma_fp16(oa[2 * nt + 1], ap[kc], b1);
        }
    }

    #pragma unroll
    for (int ni = 0; ni < 4; ni++) {
        int d0 = 8 * ni + 2 * tg;
        if (rowA < NTOK)
            *(__half2*)&out[((long)wg * NTOK + rowA) * CDIM + head * 32 + d0] =
                __floats2half2_rn(oa[ni][0], oa[ni][1]);
        if (rowB < NTOK)
            *(__half2*)&out[((long)wg * NTOK + rowB) * CDIM + head * 32 + d0] =
                __floats2half2_rn(oa[ni][2], oa[ni][3]);
    }
}

// ---------------- launch ----------------
extern "C" void kernel_launch(void* const* d_in, const int* in_sizes, int n_in,
                              void* d_out, int out_size) {
    const float* x      = (const float*)d_in[0];
    const float* qkv_w  = (const float*)d_in[1];
    const float* qkv_b  = (const float*)d_in[2];
    const float* proj_w = (const float*)d_in[3];
    const float* proj_b = (const float*)d_in[4];
    const float* rpb    = (const float*)d_in[5];
    const float* n1g    = (const float*)d_in[6];
    const float* n1b    = (const float*)d_in[7];
    const float* n2g    = (const float*)d_in[8];
    const float* n2b    = (const float*)d_in[9];
    const float* fc1_w  = (const float*)d_in[10];
    const float* fc1_b  = (const float*)d_in[11];
    const float* fc2_w  = (const float*)d_in[12];
    const float* fc2_b  = (const float*)d_in[13];
    float* out = (float*)d_out;

    __half *qkvh, *atth, *wqkv, *wproj, *wfc1, *wfc2, *biasMh;
    cudaGetSymbolAddress((void**)&qkvh, g_qkvh);
    cudaGetSymbolAddress((void**)&atth, g_atth);
    cudaGetSymbolAddress((void**)&wqkv, g_wqkv);
    cudaGetSymbolAddress((void**)&wproj, g_wproj);
    cudaGetSymbolAddress((void**)&wfc1, g_wfc1);
    cudaGetSymbolAddress((void**)&wfc2, g_wfc2);
    cudaGetSymbolAddress((void**)&biasMh, g_biasMh);

    cudaFuncSetAttribute(ln_gemm,
                         cudaFuncAttributeMaxDynamicSharedMemorySize, DSMEM_LNGEMM);
    cudaFuncSetAttribute(mega_mlp,
                         cudaFuncAttributeMaxDynamicSharedMemorySize, DSMEM_MEGA);
    cudaFuncSetAttribute(attn_mma,
                         cudaFuncAttributeMaxDynamicSharedMemorySize, DSMEM_ATT);

    convert_all<<<768, 256>>>(qkv_w, proj_w, fc1_w, fc2_w, wqkv, wproj, wfc1, wfc2);
    bias_pre<<<(NHEAD * NTOK * NTOK + 255) / 256, 256>>>(rpb, biasMh);

    ln_gemm<<<MROWS / 128, 256, DSMEM_LNGEMM>>>(x, wqkv, qkv_b, n1g, n1b, qkvh);
    attn_mma<<<dim3(BIMG * NWIN / 4, NHEAD), 512, DSMEM_ATT>>>(qkvh, biasMh, atth);
    mega_mlp<<<MROWS / 128, 256, DSMEM_MEGA>>>(
        atth, wproj, proj_b, x, n2g, n2b, wfc1, fc1_b, wfc2, fc2_b, out);
}

// round 17
// speedup vs baseline: 1.0470x; 1.0470x over previous
#include <cuda_runtime.h>
#include <cuda_fp16.h>
#include <cstdint>
#include <math.h>

#define HH 56
#define WW 56
#define WS 7
#define SH 3
#define NHEAD 4
#define HD 32
#define CDIM 128
#define NTOK 49
#define NWIN 64
#define BIMG 64
#define MROWS (BIMG * NWIN * NTOK)   // 200704
#define LSEQ (HH * WW)
#define EPS 1e-5f

// ---------------- scratch ----------------
__device__ __half g_qkvh[(size_t)MROWS * 3 * CDIM];
__device__ __half g_atth[(size_t)MROWS * CDIM];
__device__ __half g_wqkv[384 * 128];
__device__ __half g_wproj[128 * 128];
__device__ __half g_wfc1[512 * 128];
__device__ __half g_wfc2[128 * 512];
__device__ __half g_biasMh[NHEAD * NTOK * 50];   // pre-padded rows of 50

// ---------------- ptx helpers ----------------
__device__ __forceinline__ unsigned smem_u32(const void* p) {
    return (unsigned)__cvta_generic_to_shared(p);
}
__device__ __forceinline__ unsigned h2_as_u32(__half2 h) {
    return *(unsigned*)&h;
}
__device__ __forceinline__ void cp16(unsigned dst, const void* src) {
    asm volatile("cp.async.cg.shared.global [%0], [%1], 16;" :: "r"(dst), "l"(src));
}
__device__ __forceinline__ void cp_commit() { asm volatile("cp.async.commit_group;"); }
__device__ __forceinline__ void cp_wait0() { asm volatile("cp.async.wait_group 0;"); }
__device__ __forceinline__ void cp_wait1() { asm volatile("cp.async.wait_group 1;"); }

__device__ __forceinline__ void ldsm4(unsigned* r, unsigned addr) {
    asm volatile("ldmatrix.sync.aligned.m8n8.x4.shared.b16 {%0,%1,%2,%3}, [%4];"
                 : "=r"(r[0]), "=r"(r[1]), "=r"(r[2]), "=r"(r[3]) : "r"(addr));
}
__device__ __forceinline__ void ldsm4t(unsigned* r, unsigned addr) {
    asm volatile("ldmatrix.sync.aligned.m8n8.x4.trans.shared.b16 {%0,%1,%2,%3}, [%4];"
                 : "=r"(r[0]), "=r"(r[1]), "=r"(r[2]), "=r"(r[3]) : "r"(addr));
}
__device__ __forceinline__ void mma_fp16(float* d, const unsigned* a, const unsigned* b) {
    asm volatile(
        "mma.sync.aligned.m16n8k16.row.col.f32.f16.f16.f32 "
        "{%0,%1,%2,%3}, {%4,%5,%6,%7}, {%8,%9}, {%0,%1,%2,%3};\n"
        : "+f"(d[0]), "+f"(d[1]), "+f"(d[2]), "+f"(d[3])
        : "r"(a[0]), "r"(a[1]), "r"(a[2]), "r"(a[3]), "r"(b[0]), "r"(b[1]));
}

// ---------------- fused weight convert + transpose ----------------
__global__ void convert_all(const float* __restrict__ qkv_w, const float* __restrict__ proj_w,
                            const float* __restrict__ fc1_w, const float* __restrict__ fc2_w,
                            __half* __restrict__ wqkv, __half* __restrict__ wproj,
                            __half* __restrict__ wfc1, __half* __restrict__ wfc2) {
    int i = blockIdx.x * 256 + threadIdx.x;
    if (i < 49152) {
        int k = i / 384, n = i % 384;
        wqkv[n * 128 + k] = __float2half(qkv_w[i]);
    } else if (i < 65536) {
        int j = i - 49152;
        int k = j / 128, n = j % 128;
        wproj[n * 128 + k] = __float2half(proj_w[j]);
    } else if (i < 131072) {
        int j = i - 65536;
        int k = j / 512, n = j % 512;
        wfc1[n * 128 + k] = __float2half(fc1_w[j]);
    } else if (i < 196608) {
        int j = i - 131072;
        int k = j / 128, n = j % 128;
        wfc2[n * 512 + k] = __float2half(fc2_w[j]);
    }
}

// ---------------- relative-position bias precompute (half, padded rows of 50) ----------------
__global__ void bias_pre(const float* __restrict__ rpb, __half* __restrict__ biasMh) {
    int i = blockIdx.x * 256 + threadIdx.x;
    if (i < NHEAD * NTOK * 50) {
        int h = i / (NTOK * 50);
        int r = i % (NTOK * 50);
        int n = r / 50, m = r % 50;
        float v = 0.f;
        if (m < NTOK) {
            int ridx = (n / WS - m / WS + WS - 1) * (2 * WS - 1) + (n % WS - m % WS + WS - 1);
            v = rpb[ridx * NHEAD + h];
        }
        biasMh[i] = __float2half(v);
    }
}

// ============ fused LN1 + roll/partition + QKV GEMM (R14 staged version) ============
#define DSMEM_LNGEMM (34816 * 2)
__global__ void __launch_bounds__(256, 2)
ln_gemm(const float* __restrict__ X, const __half* __restrict__ Bt,
        const float* __restrict__ bias, const float* __restrict__ lng,
        const float* __restrict__ lnb, __half* __restrict__ C) {
    extern __shared__ char dyn[];
    __half (*As)[136] = (__half(*)[136])dyn;
    __half (*Bs)[136] = (__half(*)[136])(dyn + 34816);
    float (*stage)[128] = (float(*)[128])(dyn + 34816);

    const int tid = threadIdx.x;
    const int lane = tid & 31, wid = tid >> 5;
    const int m0 = blockIdx.x * 128;

    for (int rs = 0; rs < 128; rs += 32) {
        #pragma unroll
        for (int t = 0; t < 4; t++) {
            int i = tid + t * 256;
            int row = i >> 5;
            int c4 = (i & 31) * 4;
            int R = m0 + rs + row;
            int bi = R / (NWIN * NTOK);
            int tt = R % (NWIN * NTOK);
            int win = tt / NTOK, n = tt % NTOK;
            int hh = (win / 8) * WS + n / WS;
            int ww = (win % 8) * WS + n % WS;
            long srow = (long)bi * LSEQ + ((hh + SH) % HH) * WW + (ww + SH) % WW;
            *(float4*)&stage[row][c4] = *(const float4*)&X[srow * CDIM + c4];
        }
        __syncthreads();
        #pragma unroll
        for (int rr = 0; rr < 4; rr++) {
            int row = wid * 4 + rr;
            float v[4];
            #pragma unroll
            for (int t = 0; t < 4; t++) v[t] = stage[row][lane + t * 32];
            float s = v[0] + v[1] + v[2] + v[3];
            float s2 = v[0] * v[0] + v[1] * v[1] + v[2] * v[2] + v[3] * v[3];
            #pragma unroll
            for (int o = 16; o; o >>= 1) {
                s += __shfl_xor_sync(0xffffffffu, s, o);
                s2 += __shfl_xor_sync(0xffffffffu, s2, o);
            }
            float mu = s * (1.f / 128.f);
            float inv = rsqrtf(s2 * (1.f / 128.f) - mu * mu + EPS);
            #pragma unroll
            for (int t = 0; t < 4; t++) {
                int c = lane + t * 32;
                As[rs + row][c] = __float2half((v[t] - mu) * inv * lng[c] + lnb[c]);
            }
        }
        __syncthreads();
    }

    const int a_row = (lane & 7) + ((lane >> 3) & 1) * 8;
    const int a_kc  = ((lane >> 4) & 1) * 8;
    const int b_row = (lane & 7) + ((lane >> 4) & 1) * 8;
    const int b_kc  = ((lane >> 3) & 1) * 8;
    const int wm = (wid & 1) * 64;
    const int wn = (wid >> 1) * 32;
    const int g = lane >> 2, tg = lane & 3;

    for (int c = 0; c < 3; c++) {
        #pragma unroll
        for (int t = 0; t < 8; t++) {
            int i = tid + t * 256;
            int row = i >> 4;
            int col = (i & 15) * 8;
            cp16(smem_u32(&Bs[row][col]), &Bt[(long)(c * 128 + row) * CDIM + col]);
        }
        cp_commit();
        cp_wait0();
        __syncthreads();

        float acc[4][4][4];
        #pragma unroll
        for (int i = 0; i < 4; i++)
            #pragma unroll
            for (int j = 0; j < 4; j++)
                #pragma unroll
                for (int r = 0; r < 4; r++) acc[i][j][r] = 0.f;

        #pragma unroll
        for (int it = 0; it < 8; it++) {
            const int k0 = it * 16;
            unsigned a_frag[4][4], b_frag[4][2];
            #pragma unroll
            for (int mi = 0; mi < 4; mi++)
                ldsm4(a_frag[mi], smem_u32(&As[wm + mi * 16 + a_row][k0 + a_kc]));
            #pragma unroll
            for (int n2 = 0; n2 < 2; n2++) {
                unsigned r4[4];
                ldsm4(r4, smem_u32(&Bs[wn + n2 * 16 + b_row][k0 + b_kc]));
                b_frag[2 * n2][0] = r4[0]; b_frag[2 * n2][1] = r4[1];
                b_frag[2 * n2 + 1][0] = r4[2]; b_frag[2 * n2 + 1][1] = r4[3];
            }
            #pragma unroll
            for (int mi = 0; mi < 4; mi++)
                #pragma unroll
                for (int ni = 0; ni < 4; ni++)
                    mma_fp16(acc[mi][ni], a_frag[mi], b_frag[ni]);
        }
        __syncthreads();

        #pragma unroll
        for (int mi = 0; mi < 4; mi++) {
            #pragma unroll
            for (int hf = 0; hf < 2; hf++) {
                int row = m0 + wm + mi * 16 + g + hf * 8;
                #pragma unroll
                for (int ni = 0; ni < 4; ni++) {
                    int col = c * 128 + wn + ni * 8 + 2 * tg;
                    float v0 = acc[mi][ni][hf * 2 + 0] + bias[col];
                    float v1 = acc[mi][ni][hf * 2 + 1] + bias[col + 1];
                    *(__half2*)&C[(long)row * 384 + col] = __floats2half2_rn(v0, v1);
                }
            }
        }
    }
}

// ============ MEGA: proj + residual + LN2 + fc1(GELU) + fc2 + residual + scatter ============
#define DSMEM_MEGA (34816 * 3 + 4096)
__global__ void __launch_bounds__(256)
mega_mlp(const __half* __restrict__ atth, const __half* __restrict__ wproj,
         const float* __restrict__ pbias, const float* __restrict__ x,
         const float* __restrict__ lng, const float* __restrict__ lnb,
         const __half* __restrict__ wfc1, const float* __restrict__ f1bias,
         const __half* __restrict__ wfc2, const float* __restrict__ f2bias,
         float* __restrict__ out) {
    extern __shared__ char dyn[];
    __half (*As)[136] = (__half(*)[136])dyn;
    __half (*Bs)[136] = (__half(*)[136])(dyn + 34816);
    __half (*Hs)[136] = (__half(*)[136])(dyn + 69632);
    float (*redS)[128] = (float(*)[128])(dyn + 104448);
    float (*redQ)[128] = (float(*)[128])(dyn + 104448 + 2048);

    const int tid = threadIdx.x;
    const int lane = tid & 31, wid = tid >> 5;
    const int m0 = blockIdx.x * 128;

    const int a_row = (lane & 7) + ((lane >> 3) & 1) * 8;
    const int a_kc  = ((lane >> 4) & 1) * 8;
    const int b_row = (lane & 7) + ((lane >> 4) & 1) * 8;
    const int b_kc  = ((lane >> 3) & 1) * 8;
    const int wm = (wid & 1) * 64;
    const int wn = (wid >> 1) * 32;
    const int g = lane >> 2, tg = lane & 3;

    // ---- stage 1: proj GEMM ----
    #pragma unroll
    for (int t = 0; t < 8; t++) {
        int i = tid + t * 256;
        int row = i >> 4;
        int col = (i & 15) * 8;
        cp16(smem_u32(&As[row][col]), &atth[(long)(m0 + row) * CDIM + col]);
        cp16(smem_u32(&Bs[row][col]), &wproj[row * CDIM + col]);
    }
    cp_commit();
    cp_wait0();
    __syncthreads();

    float acc[4][4][4];
    #pragma unroll
    for (int i = 0; i < 4; i++)
        #pragma unroll
        for (int j = 0; j < 4; j++)
            #pragma unroll
            for (int r = 0; r < 4; r++) acc[i][j][r] = 0.f;

    #pragma unroll
    for (int it = 0; it < 8; it++) {
        const int k0 = it * 16;
        unsigned a_frag[4][4], b_frag[4][2];
        #pragma unroll
        for (int mi = 0; mi < 4; mi++)
            ldsm4(a_frag[mi], smem_u32(&As[wm + mi * 16 + a_row][k0 + a_kc]));
        #pragma unroll
        for (int n2 = 0; n2 < 2; n2++) {
            unsigned r4[4];
            ldsm4(r4, smem_u32(&Bs[wn + n2 * 16 + b_row][k0 + b_kc]));
            b_frag[2 * n2][0] = r4[0]; b_frag[2 * n2][1] = r4[1];
            b_frag[2 * n2 + 1][0] = r4[2]; b_frag[2 * n2 + 1][1] = r4[3];
        }
        #pragma unroll
        for (int mi = 0; mi < 4; mi++)
            #pragma unroll
            for (int ni = 0; ni < 4; ni++)
                mma_fp16(acc[mi][ni], a_frag[mi], b_frag[ni]);
    }
    __syncthreads();

    // ---- stage 2: y = acc + pbias + x[gather]; LN partial sums ----
    #pragma unroll
    for (int mi = 0; mi < 4; mi++) {
        #pragma unroll
        for (int hf = 0; hf < 2; hf++) {
            int lrow = wm + mi * 16 + g + hf * 8;
            int R = m0 + lrow;
            int bi = R / (NWIN * NTOK);
            int tt = R % (NWIN * NTOK);
            int win = tt / NTOK, n = tt % NTOK;
            int hh = (win / 8) * WS + n / WS;
            int ww = (win % 8) * WS + n % WS;
            long srow = (long)bi * LSEQ + ((hh + SH) % HH) * WW + (ww + SH) % WW;

            float s = 0.f, s2 = 0.f;
            #pragma unroll
            for (int ni = 0; ni < 4; ni++) {
                int col = wn + ni * 8 + 2 * tg;
                float2 xr = *(const float2*)&x[srow * CDIM + col];
                float v0 = acc[mi][ni][hf * 2 + 0] + pbias[col] + xr.x;
                float v1 = acc[mi][ni][hf * 2 + 1] + pbias[col + 1] + xr.y;
                acc[mi][ni][hf * 2 + 0] = v0;
                acc[mi][ni][hf * 2 + 1] = v1;
                s += v0 + v1;
                s2 += v0 * v0 + v1 * v1;
            }
            s += __shfl_xor_sync(0xffffffffu, s, 1);
            s += __shfl_xor_sync(0xffffffffu, s, 2);
            s2 += __shfl_xor_sync(0xffffffffu, s2, 1);
            s2 += __shfl_xor_sync(0xffffffffu, s2, 2);
            if (tg == 0) {
                redS[wid >> 1][lrow] = s;
                redQ[wid >> 1][lrow] = s2;
            }
        }
    }
    __syncthreads();

    // ---- stage 3: LN'd -> As; acc becomes out accumulator (y + fc2 bias) ----
    #pragma unroll
    for (int mi = 0; mi < 4; mi++) {
        #pragma unroll
        for (int hf = 0; hf < 2; hf++) {
            int lrow = wm + mi * 16 + g + hf * 8;
            float s = redS[0][lrow] + redS[1][lrow] + redS[2][lrow] + redS[3][lrow];
            float s2 = redQ[0][lrow] + redQ[1][lrow] + redQ[2][lrow] + redQ[3][lrow];
            float mu = s * (1.f / 128.f);
            float inv = rsqrtf(s2 * (1.f / 128.f) - mu * mu + EPS);
            #pragma unroll
            for (int ni = 0; ni < 4; ni++) {
                int col = wn + ni * 8 + 2 * tg;
                float y0 = acc[mi][ni][hf * 2 + 0];
                float y1 = acc[mi][ni][hf * 2 + 1];
                float v0 = (y0 - mu) * inv * lng[col] + lnb[col];
                float v1 = (y1 - mu) * inv * lng[col + 1] + lnb[col + 1];
                *(__half2*)&As[lrow][col] = __floats2half2_rn(v0, v1);
                acc[mi][ni][hf * 2 + 0] = y0 + f2bias[col];
                acc[mi][ni][hf * 2 + 1] = y1 + f2bias[col + 1];
            }
        }
    }
    __syncthreads();

    // ---- stage 4: 4 chunks: [wfc1->Bs, wfc2->Hs] prefetch; fc1 GEMM; GELU->Bs; fc2 GEMM ----
    for (int c = 0; c < 4; c++) {
        // issue both weight loads; fc1 gated by wait1, fc2 by wait0 later
        #pragma unroll
        for (int t = 0; t < 8; t++) {
            int i = tid + t * 256;
            int row = i >> 4;
            int col = (i & 15) * 8;
            cp16(smem_u32(&Bs[row][col]), &wfc1[(long)(c * 128 + row) * CDIM + col]);
        }
        cp_commit();
        #pragma unroll
        for (int t = 0; t < 8; t++) {
            int i = tid + t * 256;
            int row = i >> 4;
            int col = (i & 15) * 8;
            cp16(smem_u32(&Hs[row][col]), &wfc2[(long)row * 512 + c * 128 + col]);
        }
        cp_commit();
        cp_wait1();        // wfc1 ready; wfc2 still in flight
        __syncthreads();

        float fa[4][4][4];
        #pragma unroll
        for (int i = 0; i < 4; i++)
            #pragma unroll
            for (int j = 0; j < 4; j++)
                #pragma unroll
                for (int r = 0; r < 4; r++) fa[i][j][r] = 0.f;

        #pragma unroll
        for (int it = 0; it < 8; it++) {
            const int k0 = it * 16;
            unsigned a_frag[4][4], b_frag[4][2];
            #pragma unroll
            for (int mi = 0; mi < 4; mi++)
                ldsm4(a_frag[mi], smem_u32(&As[wm + mi * 16 + a_row][k0 + a_kc]));
            #pragma unroll
            for (int n2 = 0; n2 < 2; n2++) {
                unsigned r4[4];
                ldsm4(r4, smem_u32(&Bs[wn + n2 * 16 + b_row][k0 + b_kc]));
                b_frag[2 * n2][0] = r4[0]; b_frag[2 * n2][1] = r4[1];
                b_frag[2 * n2 + 1][0] = r4[2]; b_frag[2 * n2 + 1][1] = r4[3];
            }
            #pragma unroll
            for (int mi = 0; mi < 4; mi++)
                #pragma unroll
                for (int ni = 0; ni < 4; ni++)
                    mma_fp16(fa[mi][ni], a_frag[mi], b_frag[ni]);
        }
        __syncthreads();   // Bs(wfc1) reads done

        // GELU -> Bs (hid tile, A operand for fc2)
        #pragma unroll
        for (int mi = 0; mi < 4; mi++) {
            #pragma unroll
            for (int hf = 0; hf < 2; hf++) {
                int lrow = wm + mi * 16 + g + hf * 8;
                #pragma unroll
                for (int ni = 0; ni < 4; ni++) {
                    int col = c * 128 + wn + ni * 8 + 2 * tg;
                    float v0 = fa[mi][ni][hf * 2 + 0] + f1bias[col];
                    float v1 = fa[mi][ni][hf * 2 + 1] + f1bias[col + 1];
                    v0 = 0.5f * v0 * (1.0f + erff(v0 * 0.70710678118654752f));
                    v1 = 0.5f * v1 * (1.0f + erff(v1 * 0.70710678118654752f));
                    *(__half2*)&Bs[lrow][(col & 127)] = __floats2half2_rn(v0, v1);
                }
            }
        }
        cp_wait0();        // wfc2 ready in Hs
        __syncthreads();

        // acc += Bs(hid) @ Hs(wfc2)
        #pragma unroll
        for (int it = 0; it < 8; it++) {
            const int k0 = it * 16;
            unsigned a_frag[4][4], b_frag[4][2];
            #pragma unroll
            for (int mi = 0; mi < 4; mi++)
                ldsm4(a_frag[mi], smem_u32(&Bs[wm + mi * 16 + a_row][k0 + a_kc]));
            #pragma unroll
            for (int n2 = 0; n2 < 2; n2++) {
                unsigned r4[4];
                ldsm4(r4, smem_u32(&Hs[wn + n2 * 16 + b_row][k0 + b_kc]));
                b_frag[2 * n2][0] = r4[0]; b_frag[2 * n2][1] = r4[1];
                b_frag[2 * n2 + 1][0] = r4[2]; b_frag[2 * n2 + 1][1] = r4[3];
            }
            #pragma unroll
            for (int mi = 0; mi < 4; mi++)
                #pragma unroll
                for (int ni = 0; ni < 4; ni++)
                    mma_fp16(acc[mi][ni], a_frag[mi], b_frag[ni]);
        }
        __syncthreads();
    }

    // ---- stage 5: scatter out ----
    #pragma unroll
    for (int mi = 0; mi < 4; mi++) {
        #pragma unroll
        for (int hf = 0; hf < 2; hf++) {
            int R = m0 + wm + mi * 16 + g + hf * 8;
            int bi = R / (NWIN * NTOK);
            int tt = R % (NWIN * NTOK);
            int win = tt / NTOK, n = tt % NTOK;
            int hh = (win / 8) * WS + n / WS;
            int ww = (win % 8) * WS + n % WS;
            long drow = (long)bi * LSEQ + ((hh + SH) % HH) * WW + (ww + SH) % WW;
            #pragma unroll
            for (int ni = 0; ni < 4; ni++) {
                int col = wn + ni * 8 + 2 * tg;
                *(float2*)&out[drow * CDIM + col] =
                    make_float2(acc[mi][ni][hf * 2 + 0], acc[mi][ni][hf * 2 + 1]);
            }
        }
    }
}

// ============ tensor-core window attention ============
#define ATT_TILE (64 * 40)
#define ATT_SM_Q 0
#define ATT_SM_K (4 * ATT_TILE * 2)
#define ATT_SM_V (8 * ATT_TILE * 2)
#define ATT_SM_B (12 * ATT_TILE * 2)
#define ATT_SM_L (ATT_SM_B + 49 * 50 * 2 + 28)
#define DSMEM_ATT (ATT_SM_L + 4 * 64 * 4)
__global__ void __launch_bounds__(512)
attn_mma(const __half* __restrict__ qkv,
         const __half* __restrict__ biasMh,
         __half* __restrict__ out) {
    extern __shared__ char dynA[];
    __half (*Qs)[64][40] = (__half(*)[64][40])(dynA + ATT_SM_Q);
    __half (*Ks)[64][40] = (__half(*)[64][40])(dynA + ATT_SM_K);
    __half (*Vs)[64][40] = (__half(*)[64][40])(dynA + ATT_SM_V);
    __half (*bias_s)[50] = (__half(*)[50])(dynA + ATT_SM_B);
    int (*lab)[64] = (int(*)[64])(dynA + ATT_SM_L);

    const int head = blockIdx.y;
    const int tid = threadIdx.x;
    const int gtid = tid & 127;
    const int grp = tid >> 7;
    const int wg = blockIdx.x * 4 + grp;
    const int lane = tid & 31;
    const int lwid = (tid >> 5) & 3;
    const int g = lane >> 2, tg = lane & 3;

    const int wi = wg & (NWIN - 1);
    const bool need_mask = ((wi >> 3) == 7) || ((wi & 7) == 7);

    for (int i = gtid; i < 15 * 40; i += 128)
        Vs[grp][49 + i / 40][i % 40] = __float2half(0.f);

    if (need_mask && gtid < 64) {
        int t = gtid < NTOK ? gtid : 0;
        int h = (wi / 8) * WS + t / WS;
        int w = (wi % 8) * WS + t % WS;
        int rh = (h < HH - WS) ? 0 : ((h < HH - SH) ? 1 : 2);
        int rw = (w < WW - WS) ? 0 : ((w < WW - SH) ? 1 : 2);
        lab[grp][gtid] = rh * 3 + rw;
    }

    // bias table: linear copy (pre-padded rows of 50)
    for (int i = tid; i < NTOK * 50 / 2; i += 512) {
        ((__half2*)bias_s)[i] = ((const __half2*)&biasMh[head * NTOK * 50])[i];
    }

    const __half2 scale2 = __float2half2_rn(0.1767766952966369f);
    for (int i = gtid; i < NTOK * 4; i += 128) {
        int r = i >> 2, c8 = (i & 3) * 8;
        long base = ((long)wg * NTOK + r) * 384 + c8 + head * 32;
        uint4 qv = *(const uint4*)&qkv[base];
        __half2* qh = (__half2*)&qv;
        #pragma unroll
        for (int j = 0; j < 4; j++) qh[j] = __hmul2(qh[j], scale2);
        *(uint4*)&Qs[grp][r][c8] = qv;
        *(uint4*)&Ks[grp][r][c8] = *(const uint4*)&qkv[base + 128];
        *(uint4*)&Vs[grp][r][c8] = *(const uint4*)&qkv[base + 256];
    }
    __syncthreads();

    const int a_row = (lane & 7) + ((lane >> 3) & 1) * 8;
    const int a_kc  = ((lane >> 4) & 1) * 8;
    const int b_row = (lane & 7) + ((lane >> 4) & 1) * 8;
    const int b_kc  = ((lane >> 3) & 1) * 8;
    const int t_row = (lane & 7) + ((lane >> 3) & 1) * 8;
    const int t_col = (lane >> 4) * 8;
    const int w16 = lwid * 16;

    float sa[8][4];
    #pragma unroll
    for (int i = 0; i < 8; i++)
        #pragma unroll
        for (int r = 0; r < 4; r++) sa[i][r] = 0.f;

    #pragma unroll
    for (int kc = 0; kc < 2; kc++) {
        unsigned aq[4];
        ldsm4(aq, smem_u32(&Qs[grp][w16 + a_row][kc * 16 + a_kc]));
        #pragma unroll
        for (int nt = 0; nt < 4; nt++) {
            unsigned r4[4];
            ldsm4(r4, smem_u32(&Ks[grp][nt * 16 + b_row][kc * 16 + b_kc]));
            unsigned b0[2] = {r4[0], r4[1]};
            unsigned b1[2] = {r4[2], r4[3]};
            mma_fp16(sa[2 * nt], aq, b0);
            mma_fp16(sa[2 * nt + 1], aq, b1);
        }
    }

    const int rowA = w16 + g;
    const int rowB = w16 + g + 8;
    const int rA = rowA < NTOK ? rowA : 0;
    const int rB = rowB < NTOK ? rowB : 0;
    #pragma unroll
    for (int ni = 0; ni < 6; ni++) {
        float2 fA = __half22float2(*(__half2*)&bias_s[rA][8 * ni + 2 * tg]);
        float2 fB = __half22float2(*(__half2*)&bias_s[rB][8 * ni + 2 * tg]);
        sa[ni][0] += fA.x; sa[ni][1] += fA.y;
        sa[ni][2] += fB.x; sa[ni][3] += fB.y;
    }
    if (tg == 0) {
        sa[6][0] += __half2float(bias_s[rA][48]);
        sa[6][2] += __half2float(bias_s[rB][48]);
        sa[6][1] = -1e30f; sa[6][3] = -1e30f;
    } else {
        sa[6][0] = sa[6][1] = sa[6][2] = sa[6][3] = -1e30f;
    }
    sa[7][0] = sa[7][1] = sa[7][2] = sa[7][3] = -1e30f;

    if (need_mask) {
        const int labA = lab[grp][rA], labB = lab[grp][rB];
        #pragma unroll
        for (int ni = 0; ni < 7; ni++) {
            #pragma unroll
            for (int cc = 0; cc < 2; cc++) {
                int m = 8 * ni + 2 * tg + cc;
                if (m < NTOK) {
                    int lm = lab[grp][m];
                    if (lm != labA) sa[ni][cc] -= 100.f;
                    if (lm != labB) sa[ni][cc + 2] -= 100.f;
                }
            }
        }
    }

    float mxA = -1e30f, mxB = -1e30f;
    #pragma unroll
    for (int ni = 0; ni < 8; ni++) {
        mxA = fmaxf(mxA, fmaxf(sa[ni][0], sa[ni][1]));
        mxB = fmaxf(mxB, fmaxf(sa[ni][2], sa[ni][3]));
    }
    #pragma unroll
    for (int o = 1; o <= 2; o <<= 1) {
        mxA = fmaxf(mxA, __shfl_xor_sync(0xffffffffu, mxA, o));
        mxB = fmaxf(mxB, __shfl_xor_sync(0xffffffffu, mxB, o));
    }
    float smA = 0.f, smB = 0.f;
    #pragma unroll
    for (int ni = 0; ni < 8; ni++) {
        sa[ni][0] = __expf(sa[ni][0] - mxA); smA += sa[ni][0];
        sa[ni][1] = __expf(sa[ni][1] - mxA); smA += sa[ni][1];
        sa[ni][2] = __expf(sa[ni][2] - mxB); smB += sa[ni][2];
        sa[ni][3] = __expf(sa[ni][3] - mxB); smB += sa[ni][3];
    }
    #pragma unroll
    for (int o = 1; o <= 2; o <<= 1) {
        smA += __shfl_xor_sync(0xffffffffu, smA, o);
        smB += __shfl_xor_sync(0xffffffffu, smB, o);
    }
    const float ivA = 1.0f / smA, ivB = 1.0f / smB;

    unsigned ap[4][4];
    #pragma unroll
    for (int kc = 0; kc < 4; kc++) {
        ap[kc][0] = h2_as_u32(__floats2half2_rn(sa[2 * kc][0] * ivA, sa[2 * kc][1] * ivA));
        ap[kc][1] = h2_as_u32(__floats2half2_rn(sa[2 * kc][2] * ivB, sa[2 * kc][3] * ivB));
        ap[kc][2] = h2_as_u32(__floats2half2_rn(sa[2 * kc + 1][0] * ivA, sa[2 * kc + 1][1] * ivA));
        ap[kc][3] = h2_as_u32(__floats2half2_rn(sa[2 * kc + 1][2] * ivB, sa[2 * kc + 1][3] * ivB));
    }

    float oa[4][4];
    #pragma unroll
    for (int i = 0; i < 4; i++)
        #pragma unroll
        for (int r = 0; r < 4; r++) oa[i][r] = 0.f;

    #pragma unroll
    for (int kc = 0; kc < 4; kc++) {
        #pragma unroll
        for (int nt = 0; nt < 2; nt++) {
            unsigned r4[4];
            ldsm4t(r4, smem_u32(&Vs[grp][kc * 16 + t_row][nt * 16 + t_col]));
            unsigned b0[2] = {r4[0], r4[1]};
            unsigned b1[2] = {r4[2], r4[3]};
            mma_fp16(oa[2 * nt], ap[kc], b0);
            mma_fp16(oa[2 * nt + 1], ap[kc], b1);
        }
    }

    #pragma unroll
    for (int ni = 0; ni < 4; ni++) {
        int d0 = 8 * ni + 2 * tg;
        if (rowA < NTOK)
            *(__half2*)&out[((long)wg * NTOK + rowA) * CDIM + head * 32 + d0] =
                __floats2half2_rn(oa[ni][0], oa[ni][1]);
        if (rowB < NTOK)
            *(__half2*)&out[((long)wg * NTOK + rowB) * CDIM + head * 32 + d0] =
                __floats2half2_rn(oa[ni][2], oa[ni][3]);
    }
}

// ---------------- launch ----------------
extern "C" void kernel_launch(void* const* d_in, const int* in_sizes, int n_in,
                              void* d_out, int out_size) {
    const float* x      = (const float*)d_in[0];
    const float* qkv_w  = (const float*)d_in[1];
    const float* qkv_b  = (const float*)d_in[2];
    const float* proj_w = (const float*)d_in[3];
    const float* proj_b = (const float*)d_in[4];
    const float* rpb    = (const float*)d_in[5];
    const float* n1g    = (const float*)d_in[6];
    const float* n1b    = (const float*)d_in[7];
    const float* n2g    = (const float*)d_in[8];
    const float* n2b    = (const float*)d_in[9];
    const float* fc1_w  = (const float*)d_in[10];
    const float* fc1_b  = (const float*)d_in[11];
    const float* fc2_w  = (const float*)d_in[12];
    const float* fc2_b  = (const float*)d_in[13];
    float* out = (float*)d_out;

    __half *qkvh, *atth, *wqkv, *wproj, *wfc1, *wfc2, *biasMh;
    cudaGetSymbolAddress((void**)&qkvh, g_qkvh);
    cudaGetSymbolAddress((void**)&atth, g_atth);
    cudaGetSymbolAddress((void**)&wqkv, g_wqkv);
    cudaGetSymbolAddress((void**)&wproj, g_wproj);
    cudaGetSymbolAddress((void**)&wfc1, g_wfc1);
    cudaGetSymbolAddress((void**)&wfc2, g_wfc2);
    cudaGetSymbolAddress((void**)&biasMh, g_biasMh);

    cudaFuncSetAttribute(ln_gemm,
                         cudaFuncAttributeMaxDynamicSharedMemorySize, DSMEM_LNGEMM);
    cudaFuncSetAttribute(mega_mlp,
                         cudaFuncAttributeMaxDynamicSharedMemorySize, DSMEM_MEGA);
    cudaFuncSetAttribute(attn_mma,
                         cudaFuncAttributeMaxDynamicSharedMemorySize, DSMEM_ATT);

    convert_all<<<768, 256>>>(qkv_w, proj_w, fc1_w, fc2_w, wqkv, wproj, wfc1, wfc2);
    bias_pre<<<(NHEAD * NTOK * 50 + 255) / 256, 256>>>(rpb, biasMh);

    ln_gemm<<<MROWS / 128, 256, DSMEM_LNGEMM>>>(x, wqkv, qkv_b, n1g, n1b, qkvh);
    attn_mma<<<dim3(BIMG * NWIN / 4, NHEAD), 512, DSMEM_ATT>>>(qkvh, biasMh, atth);
    mega_mlp<<<MROWS / 128, 256, DSMEM_MEGA>>>(
        atth, wproj, proj_b, x, n2g, n2b, wfc1, fc1_b, wfc2, fc2_b, out);
}